// round 3
// baseline (speedup 1.0000x reference)
#include <cuda_runtime.h>
#include <cstdint>

// Problem constants
#define Bsz 64
#define Ssz 2048
#define Isz 128
#define Hsz 256
#define G4  1024   // 4*H

// ---------------------------------------------------------------------------
// Device scratch (static allocation — no cudaMalloc allowed)
// ---------------------------------------------------------------------------
__device__ __align__(16) float g_xg[(size_t)Ssz * Bsz * G4];   // [s][b][4H]  512MB
__device__ __align__(16) float g_hbuf[2][Bsz * Hsz];           // ping-pong h state
__device__ unsigned int g_bar[16 * 32];                        // per-group barrier counters (padded)

// ---------------------------------------------------------------------------
// Phase 1: xg[s][b][g*256+h] = b_g[h] + sum_i x[b][s][i] * U_g[i][h]
// Tiled fp32 GEMM: M=131072 (r = s*64+b), N=1024, K=128
// ---------------------------------------------------------------------------
#define TM 128
#define TN 64
#define KK 128
#define LDA 132
#define LDB 68
#define SMEM1 ((KK*LDA + KK*LDB) * 4)

__global__ void __launch_bounds__(256) gemm_xg_kernel(
    const float* __restrict__ x,
    const float* __restrict__ Uf, const float* __restrict__ Ui,
    const float* __restrict__ Uo, const float* __restrict__ Uc,
    const float* __restrict__ bf, const float* __restrict__ bi,
    const float* __restrict__ bo, const float* __restrict__ bc)
{
    extern __shared__ float sm[];
    float* As = sm;              // [KK][LDA]  (A transposed: As[k][m])
    float* Bs = sm + KK * LDA;   // [KK][LDB]

    const int tid = threadIdx.x;
    const int r0 = blockIdx.y * TM;
    const int j0 = blockIdx.x * TN;
    const int g  = j0 >> 8;          // which gate (tile never crosses gate boundary)
    const int hb = j0 & 255;
    const float* Ug = (g == 0) ? Uf : (g == 1) ? Ui : (g == 2) ? Uo : Uc;
    const float* bg = (g == 0) ? bf : (g == 1) ? bi : (g == 2) ? bo : bc;

    // Load A tile (128 rows x 128 k). Lanes vary over row -> conflict-free STS.
    #pragma unroll
    for (int it = 0; it < 16; it++) {
        int idx = it * 256 + tid;          // 4096 float4
        int row = idx & 127;
        int k4  = idx >> 7;                // 0..31
        int r   = r0 + row;
        int bb  = r & 63, ss = r >> 6;
        float4 v = *(const float4*)(x + ((size_t)bb * Ssz + ss) * Isz + k4 * 4);
        As[(k4*4+0)*LDA + row] = v.x;
        As[(k4*4+1)*LDA + row] = v.y;
        As[(k4*4+2)*LDA + row] = v.z;
        As[(k4*4+3)*LDA + row] = v.w;
    }
    // Load B tile (128 k x 64 n)
    #pragma unroll
    for (int it = 0; it < 8; it++) {
        int idx = it * 256 + tid;          // 2048 float4
        int n4 = idx & 15;
        int k  = idx >> 4;
        float4 v = *(const float4*)(Ug + (size_t)k * Hsz + hb + n4 * 4);
        *(float4*)(Bs + k * LDB + n4 * 4) = v;
    }
    __syncthreads();

    const int tn = tid & 15, tm = tid >> 4;
    const int m0 = tm * 8, n0 = tn * 4;

    float acc[8][4];
    #pragma unroll
    for (int i = 0; i < 8; i++)
        #pragma unroll
        for (int n = 0; n < 4; n++) acc[i][n] = 0.f;

    #pragma unroll 4
    for (int k = 0; k < KK; k++) {
        float4 b4 = *(float4*)(Bs + k * LDB + n0);
        float4 a0 = *(float4*)(As + k * LDA + m0);
        float4 a1 = *(float4*)(As + k * LDA + m0 + 4);
        float av[8] = {a0.x,a0.y,a0.z,a0.w,a1.x,a1.y,a1.z,a1.w};
        float bv[4] = {b4.x,b4.y,b4.z,b4.w};
        #pragma unroll
        for (int i = 0; i < 8; i++)
            #pragma unroll
            for (int n = 0; n < 4; n++)
                acc[i][n] += av[i] * bv[n];
    }

    float4 bias = *(const float4*)(bg + hb + n0);
    #pragma unroll
    for (int i = 0; i < 8; i++) {
        int r = r0 + m0 + i;
        float4 o;
        o.x = acc[i][0] + bias.x;
        o.y = acc[i][1] + bias.y;
        o.z = acc[i][2] + bias.z;
        o.w = acc[i][3] + bias.w;
        *(float4*)(g_xg + (size_t)r * G4 + j0 + n0) = o;
    }
}

// ---------------------------------------------------------------------------
// Phase 2: sequential LSTM scan.
// 16 groups x 8 CTAs. Group g handles batches [4g, 4g+4). CTA slice c handles
// hidx [32c, 32c+32) across all 4 gates, with its W slice (4*32*256 floats)
// resident in REGISTERS (128 floats/thread). h exchanged per step via a global
// ping-pong buffer + per-group atomic barrier (one barrier per step).
//
// Thread map (256 threads = 8 warps): warp w, lane l:
//   jsub = l & 3   -> hidx = 32*c + 4*w + jsub
//   kc   = l >> 2  -> owns interleaved k float4-chunks {kc+8t : t=0..7}
// Each thread accumulates partials for all 4 batches x 4 gates, reduced over
// the 8 kc-lanes via shfl_xor {4,8,16}. Lane with kc==b does gate math for
// batch b (c-state persistent in register).
// ---------------------------------------------------------------------------
__device__ __forceinline__ float sigf(float v) { return 1.f / (1.f + __expf(-v)); }

__global__ void init_bar_kernel() {
    if (threadIdx.x < 16) g_bar[threadIdx.x * 32] = 0u;
}

__global__ void __launch_bounds__(256, 1) lstm_scan_kernel(
    const float* __restrict__ Wf, const float* __restrict__ Wi,
    const float* __restrict__ Wo, const float* __restrict__ Wc,
    float* __restrict__ out, int write_tail)
{
    __shared__ float4 h_sm4[4][64];   // staged h for this group's 4 batches

    const int tid  = threadIdx.x;
    const int wid  = tid >> 5;
    const int lane = tid & 31;
    const int jsub = lane & 3;
    const int kc   = lane >> 2;            // 0..7
    const int grp  = blockIdx.x >> 3;      // 0..15
    const int csl  = blockIdx.x & 7;       // 0..7
    const int B0   = grp * 4;
    const int hx   = csl * 32 + wid * 4 + jsub;

    // Load W slice into registers: w[t][e][g] = W_g[k][hx], k=(kc+8t)*4+e
    float w[8][4][4];
    #pragma unroll
    for (int t = 0; t < 8; t++)
        #pragma unroll
        for (int e = 0; e < 4; e++) {
            int k = (kc + 8 * t) * 4 + e;
            size_t off = (size_t)k * Hsz + hx;
            w[t][e][0] = __ldg(Wf + off);
            w[t][e][1] = __ldg(Wi + off);
            w[t][e][2] = __ldg(Wo + off);
            w[t][e][3] = __ldg(Wc + off);
        }

    // Zero initial h (buffer 0): each CTA zeroes its own (4b x 32hx) slice.
    if (kc < 4)
        g_hbuf[0][(B0 + kc) * Hsz + hx] = 0.f;

    float c_st = 0.f, h_fin = 0.f;
    volatile unsigned int* barp = &g_bar[grp * 32];
    unsigned int ep = 1;

    // Initial group barrier (h zero-init visible to all 8 CTAs)
    __threadfence();
    __syncthreads();
    if (tid == 0) {
        atomicAdd((unsigned int*)barp, 1u);
        while (*barp < 8u) __nanosleep(32);
    }
    __syncthreads();

    for (int s = 0; s < Ssz; s++) {
        const int p = s & 1;

        // Stage h[4b][256] from global ping buffer into smem (L2-coherent loads)
        {
            int b  = tid >> 6;
            int k4 = tid & 63;
            h_sm4[b][k4] = __ldcg((const float4*)(g_hbuf[p] + (B0 + b) * Hsz + k4 * 4));
        }
        // Prefetch xg for this step (independent of h)
        float xv0 = 0.f, xv1 = 0.f, xv2 = 0.f, xv3 = 0.f;
        if (kc < 4) {
            const float* xr = g_xg + ((size_t)s * Bsz + B0 + kc) * G4 + hx;
            xv0 = __ldg(xr);
            xv1 = __ldg(xr + 256);
            xv2 = __ldg(xr + 512);
            xv3 = __ldg(xr + 768);
        }
        __syncthreads();

        // Partial GEMM over this lane's k-chunks
        float acc[4][4];
        #pragma unroll
        for (int b = 0; b < 4; b++)
            #pragma unroll
            for (int gg = 0; gg < 4; gg++) acc[b][gg] = 0.f;

        #pragma unroll
        for (int t = 0; t < 8; t++) {
            float4 hv0 = h_sm4[0][kc + 8 * t];
            float4 hv1 = h_sm4[1][kc + 8 * t];
            float4 hv2 = h_sm4[2][kc + 8 * t];
            float4 hv3 = h_sm4[3][kc + 8 * t];
            #pragma unroll
            for (int e = 0; e < 4; e++) {
                float h0 = (e == 0) ? hv0.x : (e == 1) ? hv0.y : (e == 2) ? hv0.z : hv0.w;
                float h1 = (e == 0) ? hv1.x : (e == 1) ? hv1.y : (e == 2) ? hv1.z : hv1.w;
                float h2 = (e == 0) ? hv2.x : (e == 1) ? hv2.y : (e == 2) ? hv2.z : hv2.w;
                float h3 = (e == 0) ? hv3.x : (e == 1) ? hv3.y : (e == 2) ? hv3.z : hv3.w;
                #pragma unroll
                for (int gg = 0; gg < 4; gg++) {
                    acc[0][gg] += h0 * w[t][e][gg];
                    acc[1][gg] += h1 * w[t][e][gg];
                    acc[2][gg] += h2 * w[t][e][gg];
                    acc[3][gg] += h3 * w[t][e][gg];
                }
            }
        }

        // Reduce over the 8 kc-lanes (lane bits 2..4)
        #pragma unroll
        for (int off = 4; off < 32; off <<= 1)
            #pragma unroll
            for (int b = 0; b < 4; b++)
                #pragma unroll
                for (int gg = 0; gg < 4; gg++)
                    acc[b][gg] += __shfl_xor_sync(0xffffffffu, acc[b][gg], off);

        // Gate math: lane kc==b owns batch b for this hidx
        if (kc < 4) {
            const int b = kc;
            float f  = sigf(acc[b][0] + xv0);
            float ii = sigf(acc[b][1] + xv1);
            float o  = sigf(acc[b][2] + xv2);
            float ct = sigf(acc[b][3] + xv3);   // NOTE: sigmoid candidate (per reference)
            c_st = f * c_st + ii * ct;
            float h = o * tanhf(c_st);
            h_fin = h;
            out[((size_t)(B0 + b) * Ssz + s) * Hsz + hx] = h;
            g_hbuf[1 - p][(B0 + b) * Hsz + hx] = h;
        }

        // Group barrier: all 8 CTAs' h_new visible before next step's stage
        __threadfence();
        __syncthreads();
        ep++;
        if (tid == 0) {
            atomicAdd((unsigned int*)barp, 1u);
            unsigned int tgt = 8u * ep;
            while (*barp < tgt) __nanosleep(32);
        }
        __syncthreads();
    }

    if (write_tail && kc < 4) {
        const size_t HS = (size_t)Bsz * Ssz * Hsz;
        out[HS + (size_t)(B0 + kc) * Hsz + hx] = h_fin;                       // h_T
        out[HS + (size_t)Bsz * Hsz + (size_t)(B0 + kc) * Hsz + hx] = c_st;    // c_T
    }
}

// ---------------------------------------------------------------------------
// Launch
// ---------------------------------------------------------------------------
extern "C" void kernel_launch(void* const* d_in, const int* in_sizes, int n_in,
                              void* d_out, int out_size)
{
    const float* x  = (const float*)d_in[0];
    const float* Uf = (const float*)d_in[1];
    const float* Wf = (const float*)d_in[2];
    const float* bf = (const float*)d_in[3];
    const float* Ui = (const float*)d_in[4];
    const float* Wi = (const float*)d_in[5];
    const float* bi = (const float*)d_in[6];
    const float* Uo = (const float*)d_in[7];
    const float* Wo = (const float*)d_in[8];
    const float* bo = (const float*)d_in[9];
    const float* Uc = (const float*)d_in[10];
    const float* Wc = (const float*)d_in[11];
    const float* bc = (const float*)d_in[12];
    float* out = (float*)d_out;

    (void)in_sizes; (void)n_in;

    // hidden_seq (B*S*H) always; h_T + c_T only if the out buffer includes them
    const long long full = (long long)Bsz * Ssz * Hsz + 2LL * Bsz * Hsz;
    int write_tail = ((long long)out_size >= full) ? 1 : 0;

    cudaFuncSetAttribute(gemm_xg_kernel,
                         cudaFuncAttributeMaxDynamicSharedMemorySize, SMEM1);

    // Reset barrier counters (graph-replay safe), then phase 1, then scan.
    init_bar_kernel<<<1, 32>>>();
    gemm_xg_kernel<<<dim3(16, 1024), 256, SMEM1>>>(x, Uf, Ui, Uo, Uc, bf, bi, bo, bc);
    lstm_scan_kernel<<<128, 256>>>(Wf, Wi, Wo, Wc, out, write_tail);
}